// round 14
// baseline (speedup 1.0000x reference)
#include <cuda_runtime.h>
#include <math.h>

#define D_DIM 1024
#define F_DIM 4096
#define E_DIM 8
#define NTOK  16384               // B*S
#define NFB   128                 // f-blocks in kernel A (32 rows each)
#define ROWS_PER_FB 32
#define ROWS_PER_TH 16            // two row-halves per CTA

// ---------------- device scratch ----------------
__device__ __align__(16) float g_part[NFB][5][D_DIM];   // 2.5 MB
__device__ __align__(16) float g_sum[5][D_DIM];         // raw F-sums
__device__ float g_bias_mean;

__device__ __forceinline__ void acc4(float4& s, float4 v)           { s.x += v.x; s.y += v.y; s.z += v.z; s.w += v.w; }
__device__ __forceinline__ void fma4(float4& s, float4 a, float4 b) { s.x = fmaf(a.x,b.x,s.x); s.y = fmaf(a.y,b.y,s.y); s.z = fmaf(a.z,b.z,s.z); s.w = fmaf(a.w,b.w,s.w); }
__device__ __forceinline__ float dot4(float4 a, float4 b, float acc) {
    return fmaf(a.x, b.x, fmaf(a.y, b.y, fmaf(a.z, b.z, fmaf(a.w, b.w, acc))));
}

// ---------------- kernel A: W moments (router-style ping-pong) -------------
// grid 128, block 512. Thread = (row-half h, f4col q); 16 rows x 2 mats.
// Chunks of 4 rows; two buffer BANKS (bufb/bufw)[2][4], consume bank c&1
// while refilling it with chunk c+2 — the exact structure ptxas preserved
// in k_router (127 regs there vs 62 when expressed as one rotating array).
__global__ void __launch_bounds__(512) k_reduceW(const float* __restrict__ Wb,
                                                 const float* __restrict__ Wd) {
    const int q = threadIdx.x & 255;            // f4col 0..255
    const int h = threadIdx.x >> 8;             // row half 0..1
    const size_t base = ((size_t)blockIdx.x * ROWS_PER_FB + h * ROWS_PER_TH) * 256 + q;
    const float4* pb = reinterpret_cast<const float4*>(Wb) + base;
    const float4* pw = reinterpret_cast<const float4*>(Wd) + base;

    float4 sb = {0,0,0,0}, sd = {0,0,0,0}, sbb = {0,0,0,0}, sbd = {0,0,0,0}, sdd = {0,0,0,0};

    // preload chunks 0 and 1 (rows 0..7 of both mats): 16 LDG.128 in flight
    float4 bufb[2][4], bufw[2][4];
#pragma unroll
    for (int p = 0; p < 2; p++)
#pragma unroll
        for (int t = 0; t < 4; t++) {
            bufb[p][t] = pb[(size_t)(p * 4 + t) * 256];
            bufw[p][t] = pw[(size_t)(p * 4 + t) * 256];
        }

#pragma unroll
    for (int c = 0; c < 4; c++) {               // 4 chunks x 4 rows = 16 rows
#pragma unroll
        for (int t = 0; t < 4; t++) {
            float4 b = bufb[c & 1][t];
            float4 w = bufw[c & 1][t];
            // refill this slot with chunk c+2 immediately after last use
            if (c < 2) {
                bufb[c & 1][t] = pb[(size_t)((c + 2) * 4 + t) * 256];
                bufw[c & 1][t] = pw[(size_t)((c + 2) * 4 + t) * 256];
            }
            acc4(sb, b); acc4(sd, w);
            fma4(sbb, b, b); fma4(sbd, b, w); fma4(sdd, w, w);
        }
    }

    // combine the two row-halves via smem (one stat at a time, 4KB buffer)
    __shared__ float4 red[256];
    const int c = blockIdx.x;
    float4 part[5] = {sb, sd, sbb, sbd, sdd};
#pragma unroll
    for (int k = 0; k < 5; k++) {
        if (h == 1) red[q] = part[k];
        __syncthreads();
        if (h == 0) {
            float4 t = part[k];
            acc4(t, red[q]);
            *reinterpret_cast<float4*>(&g_part[c][k][q * 4]) = t;
        }
        __syncthreads();
    }
}

// ---------------- kernel B: reduce 128 partials + bias mean ----------------
// grid (8 coltiles, 6), block 256 = 8 chunk-groups x 32 f4cols.
__global__ void __launch_bounds__(256) k_sum(const float* __restrict__ bias) {
    const int k = blockIdx.y;
    if (k < 5) {
        const int lane = threadIdx.x & 31;          // f4col within tile
        const int g    = threadIdx.x >> 5;          // chunk group 0..7
        const int qg   = blockIdx.x * 32 + lane;    // f4col 0..255
        float4 s = make_float4(0, 0, 0, 0);
#pragma unroll
        for (int i = 0; i < 16; i++)
            acc4(s, *reinterpret_cast<const float4*>(&g_part[g * 16 + i][k][qg * 4]));
        __shared__ float4 red[8][32];
        red[g][lane] = s;
        __syncthreads();
        if (g == 0) {
            float4 t = red[0][lane];
#pragma unroll
            for (int j = 1; j < 8; j++) acc4(t, red[j][lane]);
            *reinterpret_cast<float4*>(&g_sum[k][qg * 4]) = t;
        }
    } else if (blockIdx.x == 0) {
        __shared__ float sh[8];
        const float4* b4 = reinterpret_cast<const float4*>(bias);
        float s = 0.f;
#pragma unroll
        for (int i = 0; i < 4; i++) {
            float4 v = b4[threadIdx.x + i * 256];
            s += (v.x + v.y) + (v.z + v.w);
        }
#pragma unroll
        for (int o = 16; o > 0; o >>= 1) s += __shfl_xor_sync(0xffffffffu, s, o);
        if ((threadIdx.x & 31) == 0) sh[threadIdx.x >> 5] = s;
        __syncthreads();
        if (threadIdx.x == 0) {
            float t = 0.f;
#pragma unroll
            for (int i = 0; i < 8; i++) t += sh[i];
            g_bias_mean = t * (1.0f / (float)F_DIM);
        }
    }
}

// ---------------- kernel C: fused router (8 tok/warp, depth-2) -------------
// Unchanged from R10-R12 — verified correct, ~12us.
__global__ void k_router(const float* __restrict__ x,
                         const float* __restrict__ alpha,
                         const float* __restrict__ beta,
                         float* __restrict__ out) {
    __shared__ __align__(16) float sh[5][D_DIM];     // 20 KB
    __shared__ float sred[4][8][5];

    // stage raw sums -> centered stats in shared (each block identically)
    {
        const float inv = 1.0f / (float)F_DIM;
#pragma unroll
        for (int j = 0; j < 2; j++) {
            const int q = threadIdx.x + j * 128;     // f4col 0..255
            float4 s0 = *reinterpret_cast<const float4*>(&g_sum[0][q * 4]);
            float4 s1 = *reinterpret_cast<const float4*>(&g_sum[1][q * 4]);
            float4 s2 = *reinterpret_cast<const float4*>(&g_sum[2][q * 4]);
            float4 s3 = *reinterpret_cast<const float4*>(&g_sum[3][q * 4]);
            float4 s4 = *reinterpret_cast<const float4*>(&g_sum[4][q * 4]);
            float4 mb, md, cbb, cbd, cdd;
            mb.x = s0.x*inv; mb.y = s0.y*inv; mb.z = s0.z*inv; mb.w = s0.w*inv;
            md.x = s1.x*inv; md.y = s1.y*inv; md.z = s1.z*inv; md.w = s1.w*inv;
            cbb.x = s2.x*inv - mb.x*mb.x; cbb.y = s2.y*inv - mb.y*mb.y;
            cbb.z = s2.z*inv - mb.z*mb.z; cbb.w = s2.w*inv - mb.w*mb.w;
            cbd.x = s3.x*inv - mb.x*md.x; cbd.y = s3.y*inv - mb.y*md.y;
            cbd.z = s3.z*inv - mb.z*md.z; cbd.w = s3.w*inv - mb.w*md.w;
            cdd.x = s4.x*inv - md.x*md.x; cdd.y = s4.y*inv - md.y*md.y;
            cdd.z = s4.z*inv - md.z*md.z; cdd.w = s4.w*inv - md.w*md.w;
            *reinterpret_cast<float4*>(&sh[0][q * 4]) = mb;
            *reinterpret_cast<float4*>(&sh[1][q * 4]) = md;
            *reinterpret_cast<float4*>(&sh[2][q * 4]) = cbb;
            *reinterpret_cast<float4*>(&sh[3][q * 4]) = cbd;
            *reinterpret_cast<float4*>(&sh[4][q * 4]) = cdd;
        }
    }
    __syncthreads();

    const int lane = threadIdx.x & 31;
    const int wid  = threadIdx.x >> 5;
    const int tok0 = (blockIdx.x * 4 + wid) * 8;
    const float* xp = x + (size_t)tok0 * D_DIM + lane * 4;   // lane offset baked in

    float acc[8][5];
#pragma unroll
    for (int t = 0; t < 8; t++)
#pragma unroll
        for (int s = 0; s < 5; s++) acc[t][s] = 0.f;

    // preload chunks 0 and 1: 16 LDG.128 in flight
    float4 buf[2][8];
#pragma unroll
    for (int p = 0; p < 2; p++)
#pragma unroll
        for (int t = 0; t < 8; t++)
            buf[p][t] = *reinterpret_cast<const float4*>(xp + (size_t)t * D_DIM + p * 128);

#pragma unroll
    for (int c = 0; c < 8; c++) {
        const int off = c * 128 + lane * 4;      // shared-mem offset (lane included)
        const int nchunk = (c + 2) * 128;        // x refill offset (xp has lane*4)
        float4 s0 = *reinterpret_cast<const float4*>(&sh[0][off]);
        float4 s1 = *reinterpret_cast<const float4*>(&sh[1][off]);
        float4 s2 = *reinterpret_cast<const float4*>(&sh[2][off]);
        float4 s3 = *reinterpret_cast<const float4*>(&sh[3][off]);
        float4 s4 = *reinterpret_cast<const float4*>(&sh[4][off]);
#pragma unroll
        for (int t = 0; t < 8; t++) {
            float4 v = buf[c & 1][t];
            // refill slot t with chunk c+2 immediately after last use
            if (c < 6)
                buf[c & 1][t] = *reinterpret_cast<const float4*>(
                    xp + (size_t)t * D_DIM + nchunk);
            float4 q;
            q.x = v.x * v.x; q.y = v.y * v.y; q.z = v.z * v.z; q.w = v.w * v.w;
            acc[t][0] = dot4(v, s0, acc[t][0]);
            acc[t][1] = dot4(v, s1, acc[t][1]);
            acc[t][2] = dot4(q, s2, acc[t][2]);
            acc[t][3] = dot4(q, s3, acc[t][3]);
            acc[t][4] = dot4(q, s4, acc[t][4]);
        }
    }

    // warp reductions: token t's 5 sums land on lane t
#pragma unroll
    for (int t = 0; t < 8; t++) {
        float v0 = acc[t][0], v1 = acc[t][1], v2 = acc[t][2], v3 = acc[t][3], v4 = acc[t][4];
#pragma unroll
        for (int o = 16; o > 0; o >>= 1) {
            v0 += __shfl_xor_sync(0xffffffffu, v0, o);
            v1 += __shfl_xor_sync(0xffffffffu, v1, o);
            v2 += __shfl_xor_sync(0xffffffffu, v2, o);
            v3 += __shfl_xor_sync(0xffffffffu, v3, o);
            v4 += __shfl_xor_sync(0xffffffffu, v4, o);
        }
        if (lane == t) {
            sred[wid][t][0] = v0;
            sred[wid][t][1] = v1;
            sred[wid][t][2] = v2;
            sred[wid][t][3] = v3;
            sred[wid][t][4] = v4;
        }
    }
    __syncthreads();

    // epilogue: one thread per token (32 tokens/block)
    if (threadIdx.x < 32) {
        const int w = threadIdx.x >> 3;
        const int t = threadIdx.x & 7;
        const int tok = blockIdx.x * 32 + threadIdx.x;
        const float bm = g_bias_mean;

        const float d_mb = sred[w][t][0];
        const float d_md = sred[w][t][1];
        const float d_bb = sred[w][t][2];
        const float d_bd = sred[w][t][3];
        const float d_dd = sred[w][t][4];

        float l[E_DIM];
#pragma unroll
        for (int e = 0; e < E_DIM; e++) {
            float a = __ldg(&alpha[e]);
            float b = __ldg(&beta[e]);
            float mu = fmaf(a, d_mb, fmaf(b, d_md, bm));
            float va = fmaf(a * a, d_bb, fmaf(2.0f * a * b, d_bd, b * b * d_dd));
            float z  = mu * rsqrtf(va + 1e-8f) * 0.70710678118654752f;
            l[e] = erff(z);
        }

        // top-2 (strict >, ties keep lower index — matches lax.top_k)
        int i1 = -1, i2 = -1;
        float v1 = -2.0f, v2 = -2.0f;
#pragma unroll
        for (int e = 0; e < E_DIM; e++) {
            float val = l[e];
            if (val > v1)      { v2 = v1; i2 = i1; v1 = val; i1 = e; }
            else if (val > v2) { v2 = val; i2 = e; }
        }
        float w2 = 1.0f / (1.0f + expf(v1 - v2));
        float w1 = 1.0f - w2;

        float wv[E_DIM];
#pragma unroll
        for (int e = 0; e < E_DIM; e++)
            wv[e] = (e == i1) ? w1 : ((e == i2) ? w2 : 0.0f);

        float4* ow = reinterpret_cast<float4*>(out + (size_t)tok * E_DIM);
        ow[0] = make_float4(wv[0], wv[1], wv[2], wv[3]);
        ow[1] = make_float4(wv[4], wv[5], wv[6], wv[7]);
        float4* ol = reinterpret_cast<float4*>(out + (size_t)NTOK * E_DIM + (size_t)tok * E_DIM);
        ol[0] = make_float4(l[0], l[1], l[2], l[3]);
        ol[1] = make_float4(l[4], l[5], l[6], l[7]);
    }
}

// ---------------- launch ---------------------------------------------------
extern "C" void kernel_launch(void* const* d_in, const int* in_sizes, int n_in,
                              void* d_out, int out_size) {
    const float* x     = (const float*)d_in[0];
    const float* Wb    = (const float*)d_in[1];
    const float* Wd    = (const float*)d_in[2];
    const float* bias  = (const float*)d_in[3];
    const float* alpha = (const float*)d_in[4];
    const float* beta  = (const float*)d_in[5];
    float* out = (float*)d_out;

    k_reduceW<<<NFB, 512>>>(Wb, Wd);
    k_sum<<<dim3(8, 6), 256>>>(bias);
    k_router<<<NTOK / 32, 128>>>(x, alpha, beta, out);
}

// round 15
// speedup vs baseline: 1.0721x; 1.0721x over previous
#include <cuda_runtime.h>
#include <math.h>

#define D_DIM 1024
#define F_DIM 4096
#define E_DIM 8
#define NTOK  16384               // B*S
#define NFB   128                 // f-blocks in kernel A (32 rows each)
#define ROWS_PER_FB 32
#define ROWS_PER_TH 16            // two row-halves per CTA

// ---------------- device scratch ----------------
__device__ __align__(16) float g_part[NFB][5][D_DIM];   // 2.5 MB
__device__ __align__(16) float g_sum[5][D_DIM];         // raw F-sums
__device__ float g_bias_mean;

__device__ __forceinline__ void acc4(float4& s, float4 v)           { s.x += v.x; s.y += v.y; s.z += v.z; s.w += v.w; }
__device__ __forceinline__ void fma4(float4& s, float4 a, float4 b) { s.x = fmaf(a.x,b.x,s.x); s.y = fmaf(a.y,b.y,s.y); s.z = fmaf(a.z,b.z,s.z); s.w = fmaf(a.w,b.w,s.w); }
__device__ __forceinline__ float dot4(float4 a, float4 b, float acc) {
    return fmaf(a.x, b.x, fmaf(a.y, b.y, fmaf(a.z, b.z, fmaf(a.w, b.w, acc))));
}

// ---------------- kernel A: W moments (ping-pong, FULL reg budget) ---------
// grid 128, block 512, minBlocks=1: grid is single-wave (128 < 148 SMs), so a
// second resident CTA/SM is useless — tell ptxas so it stops capping regs at
// 62 (= 64K/(512*2) heuristic) and keeps the 16-load pipeline live.
__global__ void __launch_bounds__(512, 1) k_reduceW(const float* __restrict__ Wb,
                                                    const float* __restrict__ Wd) {
    const int q = threadIdx.x & 255;            // f4col 0..255
    const int h = threadIdx.x >> 8;             // row half 0..1
    const size_t base = ((size_t)blockIdx.x * ROWS_PER_FB + h * ROWS_PER_TH) * 256 + q;
    const float4* pb = reinterpret_cast<const float4*>(Wb) + base;
    const float4* pw = reinterpret_cast<const float4*>(Wd) + base;

    float4 sb = {0,0,0,0}, sd = {0,0,0,0}, sbb = {0,0,0,0}, sbd = {0,0,0,0}, sdd = {0,0,0,0};

    // preload chunks 0 and 1 (rows 0..7 of both mats): 16 LDG.128 in flight
    float4 bufb[2][4], bufw[2][4];
#pragma unroll
    for (int p = 0; p < 2; p++)
#pragma unroll
        for (int t = 0; t < 4; t++) {
            bufb[p][t] = pb[(size_t)(p * 4 + t) * 256];
            bufw[p][t] = pw[(size_t)(p * 4 + t) * 256];
        }

#pragma unroll
    for (int c = 0; c < 4; c++) {               // 4 chunks x 4 rows = 16 rows
#pragma unroll
        for (int t = 0; t < 4; t++) {
            float4 b = bufb[c & 1][t];
            float4 w = bufw[c & 1][t];
            // refill this slot with chunk c+2 immediately after last use
            if (c < 2) {
                bufb[c & 1][t] = pb[(size_t)((c + 2) * 4 + t) * 256];
                bufw[c & 1][t] = pw[(size_t)((c + 2) * 4 + t) * 256];
            }
            acc4(sb, b); acc4(sd, w);
            fma4(sbb, b, b); fma4(sbd, b, w); fma4(sdd, w, w);
        }
    }

    // combine the two row-halves via smem (one stat at a time, 4KB buffer)
    __shared__ float4 red[256];
    const int c = blockIdx.x;
    float4 part[5] = {sb, sd, sbb, sbd, sdd};
#pragma unroll
    for (int k = 0; k < 5; k++) {
        if (h == 1) red[q] = part[k];
        __syncthreads();
        if (h == 0) {
            float4 t = part[k];
            acc4(t, red[q]);
            *reinterpret_cast<float4*>(&g_part[c][k][q * 4]) = t;
        }
        __syncthreads();
    }
}

// ---------------- kernel B: reduce 128 partials + bias mean ----------------
// grid (8 coltiles, 6), block 256 = 8 chunk-groups x 32 f4cols.
__global__ void __launch_bounds__(256) k_sum(const float* __restrict__ bias) {
    const int k = blockIdx.y;
    if (k < 5) {
        const int lane = threadIdx.x & 31;          // f4col within tile
        const int g    = threadIdx.x >> 5;          // chunk group 0..7
        const int qg   = blockIdx.x * 32 + lane;    // f4col 0..255
        float4 s = make_float4(0, 0, 0, 0);
#pragma unroll
        for (int i = 0; i < 16; i++)
            acc4(s, *reinterpret_cast<const float4*>(&g_part[g * 16 + i][k][qg * 4]));
        __shared__ float4 red[8][32];
        red[g][lane] = s;
        __syncthreads();
        if (g == 0) {
            float4 t = red[0][lane];
#pragma unroll
            for (int j = 1; j < 8; j++) acc4(t, red[j][lane]);
            *reinterpret_cast<float4*>(&g_sum[k][qg * 4]) = t;
        }
    } else if (blockIdx.x == 0) {
        __shared__ float sh[8];
        const float4* b4 = reinterpret_cast<const float4*>(bias);
        float s = 0.f;
#pragma unroll
        for (int i = 0; i < 4; i++) {
            float4 v = b4[threadIdx.x + i * 256];
            s += (v.x + v.y) + (v.z + v.w);
        }
#pragma unroll
        for (int o = 16; o > 0; o >>= 1) s += __shfl_xor_sync(0xffffffffu, s, o);
        if ((threadIdx.x & 31) == 0) sh[threadIdx.x >> 5] = s;
        __syncthreads();
        if (threadIdx.x == 0) {
            float t = 0.f;
#pragma unroll
            for (int i = 0; i < 8; i++) t += sh[i];
            g_bias_mean = t * (1.0f / (float)F_DIM);
        }
    }
}

// ---------------- kernel C: fused router (8 tok/warp, depth-2) -------------
// Unchanged from R10-R14 — verified correct, ~12us.
__global__ void k_router(const float* __restrict__ x,
                         const float* __restrict__ alpha,
                         const float* __restrict__ beta,
                         float* __restrict__ out) {
    __shared__ __align__(16) float sh[5][D_DIM];     // 20 KB
    __shared__ float sred[4][8][5];

    // stage raw sums -> centered stats in shared (each block identically)
    {
        const float inv = 1.0f / (float)F_DIM;
#pragma unroll
        for (int j = 0; j < 2; j++) {
            const int q = threadIdx.x + j * 128;     // f4col 0..255
            float4 s0 = *reinterpret_cast<const float4*>(&g_sum[0][q * 4]);
            float4 s1 = *reinterpret_cast<const float4*>(&g_sum[1][q * 4]);
            float4 s2 = *reinterpret_cast<const float4*>(&g_sum[2][q * 4]);
            float4 s3 = *reinterpret_cast<const float4*>(&g_sum[3][q * 4]);
            float4 s4 = *reinterpret_cast<const float4*>(&g_sum[4][q * 4]);
            float4 mb, md, cbb, cbd, cdd;
            mb.x = s0.x*inv; mb.y = s0.y*inv; mb.z = s0.z*inv; mb.w = s0.w*inv;
            md.x = s1.x*inv; md.y = s1.y*inv; md.z = s1.z*inv; md.w = s1.w*inv;
            cbb.x = s2.x*inv - mb.x*mb.x; cbb.y = s2.y*inv - mb.y*mb.y;
            cbb.z = s2.z*inv - mb.z*mb.z; cbb.w = s2.w*inv - mb.w*mb.w;
            cbd.x = s3.x*inv - mb.x*md.x; cbd.y = s3.y*inv - mb.y*md.y;
            cbd.z = s3.z*inv - mb.z*md.z; cbd.w = s3.w*inv - mb.w*md.w;
            cdd.x = s4.x*inv - md.x*md.x; cdd.y = s4.y*inv - md.y*md.y;
            cdd.z = s4.z*inv - md.z*md.z; cdd.w = s4.w*inv - md.w*md.w;
            *reinterpret_cast<float4*>(&sh[0][q * 4]) = mb;
            *reinterpret_cast<float4*>(&sh[1][q * 4]) = md;
            *reinterpret_cast<float4*>(&sh[2][q * 4]) = cbb;
            *reinterpret_cast<float4*>(&sh[3][q * 4]) = cbd;
            *reinterpret_cast<float4*>(&sh[4][q * 4]) = cdd;
        }
    }
    __syncthreads();

    const int lane = threadIdx.x & 31;
    const int wid  = threadIdx.x >> 5;
    const int tok0 = (blockIdx.x * 4 + wid) * 8;
    const float* xp = x + (size_t)tok0 * D_DIM + lane * 4;   // lane offset baked in

    float acc[8][5];
#pragma unroll
    for (int t = 0; t < 8; t++)
#pragma unroll
        for (int s = 0; s < 5; s++) acc[t][s] = 0.f;

    // preload chunks 0 and 1: 16 LDG.128 in flight
    float4 buf[2][8];
#pragma unroll
    for (int p = 0; p < 2; p++)
#pragma unroll
        for (int t = 0; t < 8; t++)
            buf[p][t] = *reinterpret_cast<const float4*>(xp + (size_t)t * D_DIM + p * 128);

#pragma unroll
    for (int c = 0; c < 8; c++) {
        const int off = c * 128 + lane * 4;      // shared-mem offset (lane included)
        const int nchunk = (c + 2) * 128;        // x refill offset (xp has lane*4)
        float4 s0 = *reinterpret_cast<const float4*>(&sh[0][off]);
        float4 s1 = *reinterpret_cast<const float4*>(&sh[1][off]);
        float4 s2 = *reinterpret_cast<const float4*>(&sh[2][off]);
        float4 s3 = *reinterpret_cast<const float4*>(&sh[3][off]);
        float4 s4 = *reinterpret_cast<const float4*>(&sh[4][off]);
#pragma unroll
        for (int t = 0; t < 8; t++) {
            float4 v = buf[c & 1][t];
            // refill slot t with chunk c+2 immediately after last use
            if (c < 6)
                buf[c & 1][t] = *reinterpret_cast<const float4*>(
                    xp + (size_t)t * D_DIM + nchunk);
            float4 q;
            q.x = v.x * v.x; q.y = v.y * v.y; q.z = v.z * v.z; q.w = v.w * v.w;
            acc[t][0] = dot4(v, s0, acc[t][0]);
            acc[t][1] = dot4(v, s1, acc[t][1]);
            acc[t][2] = dot4(q, s2, acc[t][2]);
            acc[t][3] = dot4(q, s3, acc[t][3]);
            acc[t][4] = dot4(q, s4, acc[t][4]);
        }
    }

    // warp reductions: token t's 5 sums land on lane t
#pragma unroll
    for (int t = 0; t < 8; t++) {
        float v0 = acc[t][0], v1 = acc[t][1], v2 = acc[t][2], v3 = acc[t][3], v4 = acc[t][4];
#pragma unroll
        for (int o = 16; o > 0; o >>= 1) {
            v0 += __shfl_xor_sync(0xffffffffu, v0, o);
            v1 += __shfl_xor_sync(0xffffffffu, v1, o);
            v2 += __shfl_xor_sync(0xffffffffu, v2, o);
            v3 += __shfl_xor_sync(0xffffffffu, v3, o);
            v4 += __shfl_xor_sync(0xffffffffu, v4, o);
        }
        if (lane == t) {
            sred[wid][t][0] = v0;
            sred[wid][t][1] = v1;
            sred[wid][t][2] = v2;
            sred[wid][t][3] = v3;
            sred[wid][t][4] = v4;
        }
    }
    __syncthreads();

    // epilogue: one thread per token (32 tokens/block)
    if (threadIdx.x < 32) {
        const int w = threadIdx.x >> 3;
        const int t = threadIdx.x & 7;
        const int tok = blockIdx.x * 32 + threadIdx.x;
        const float bm = g_bias_mean;

        const float d_mb = sred[w][t][0];
        const float d_md = sred[w][t][1];
        const float d_bb = sred[w][t][2];
        const float d_bd = sred[w][t][3];
        const float d_dd = sred[w][t][4];

        float l[E_DIM];
#pragma unroll
        for (int e = 0; e < E_DIM; e++) {
            float a = __ldg(&alpha[e]);
            float b = __ldg(&beta[e]);
            float mu = fmaf(a, d_mb, fmaf(b, d_md, bm));
            float va = fmaf(a * a, d_bb, fmaf(2.0f * a * b, d_bd, b * b * d_dd));
            float z  = mu * rsqrtf(va + 1e-8f) * 0.70710678118654752f;
            l[e] = erff(z);
        }

        // top-2 (strict >, ties keep lower index — matches lax.top_k)
        int i1 = -1, i2 = -1;
        float v1 = -2.0f, v2 = -2.0f;
#pragma unroll
        for (int e = 0; e < E_DIM; e++) {
            float val = l[e];
            if (val > v1)      { v2 = v1; i2 = i1; v1 = val; i1 = e; }
            else if (val > v2) { v2 = val; i2 = e; }
        }
        float w2 = 1.0f / (1.0f + expf(v1 - v2));
        float w1 = 1.0f - w2;

        float wv[E_DIM];
#pragma unroll
        for (int e = 0; e < E_DIM; e++)
            wv[e] = (e == i1) ? w1 : ((e == i2) ? w2 : 0.0f);

        float4* ow = reinterpret_cast<float4*>(out + (size_t)tok * E_DIM);
        ow[0] = make_float4(wv[0], wv[1], wv[2], wv[3]);
        ow[1] = make_float4(wv[4], wv[5], wv[6], wv[7]);
        float4* ol = reinterpret_cast<float4*>(out + (size_t)NTOK * E_DIM + (size_t)tok * E_DIM);
        ol[0] = make_float4(l[0], l[1], l[2], l[3]);
        ol[1] = make_float4(l[4], l[5], l[6], l[7]);
    }
}

// ---------------- launch ---------------------------------------------------
extern "C" void kernel_launch(void* const* d_in, const int* in_sizes, int n_in,
                              void* d_out, int out_size) {
    const float* x     = (const float*)d_in[0];
    const float* Wb    = (const float*)d_in[1];
    const float* Wd    = (const float*)d_in[2];
    const float* bias  = (const float*)d_in[3];
    const float* alpha = (const float*)d_in[4];
    const float* beta  = (const float*)d_in[5];
    float* out = (float*)d_out;

    k_reduceW<<<NFB, 512>>>(Wb, Wd);
    k_sum<<<dim3(8, 6), 256>>>(bias);
    k_router<<<NTOK / 32, 128>>>(x, alpha, beta, out);
}